// round 15
// baseline (speedup 1.0000x reference)
#include <cuda_runtime.h>
#include <cuda_bf16.h>
#include <math.h>
#include <stdint.h>

// Problem constants (fixed by the reference)
#define NN   50000
#define EE   400000
#define FIN  128
#define NH   3
#define DD   64
#define HD   192   // NH*DD
#define GG   64
#define PP   64

// ---------------- scratch (device globals; no allocation) ----------------
__device__ __nv_bfloat16 g_fs[(size_t)NN * HD];   // GEMM outputs, bf16
__device__ __nv_bfloat16 g_fd[(size_t)NN * HD];
__device__ __nv_bfloat16 g_xb[(size_t)NN * HD];   // bf16 activations (GEMM A input)
__device__ __nv_bfloat16 g_wT[6 * HD * HD];       // 6 transposed bf16 weight mats [N][K]
__device__ float g_gsum[GG * DD];
__device__ float g_gcnt[GG];
// CSR by dst (rebuilt every launch)
__device__ int g_deg[NN];
__device__ int g_off[NN + 1];
__device__ int g_cur[NN];
__device__ int g_esrc[EE];

static inline int cdiv(int a, int b) { return (a + b - 1) / b; }

// ---------------- CSR build (4 kernels, run on side stream) ----------------
__global__ void k_init() {
    int idx = blockIdx.x * blockDim.x + threadIdx.x;
    if (idx < NN) g_deg[idx] = 0;
    if (idx < GG * DD) g_gsum[idx] = 0.0f;
    if (idx < GG) g_gcnt[idx] = 0.0f;
}

__global__ void k_hist(const int* __restrict__ dst) {
    int e = blockIdx.x * blockDim.x + threadIdx.x;
    if (e < EE) atomicAdd(&g_deg[dst[e]], 1);
}

__global__ void k_scan() {
    __shared__ int s_warp[32];
    int tid = threadIdx.x;
    int lane = tid & 31, wid = tid >> 5;
    int running = 0;
    for (int base = 0; base < NN; base += 1024) {
        int i = base + tid;
        int v = (i < NN) ? g_deg[i] : 0;
        int x = v;
#pragma unroll
        for (int o = 1; o < 32; o <<= 1) {
            int y = __shfl_up_sync(0xFFFFFFFFu, x, o);
            if (lane >= o) x += y;
        }
        if (lane == 31) s_warp[wid] = x;
        __syncthreads();
        if (wid == 0) {
            int w = s_warp[lane];
#pragma unroll
            for (int o = 1; o < 32; o <<= 1) {
                int y = __shfl_up_sync(0xFFFFFFFFu, w, o);
                if (lane >= o) w += y;
            }
            s_warp[lane] = w;
        }
        __syncthreads();
        int excl = running + x - v + (wid > 0 ? s_warp[wid - 1] : 0);
        if (i < NN) { g_off[i] = excl; g_cur[i] = excl; }
        int total = s_warp[31];
        __syncthreads();
        running += total;
    }
    if (tid == 0) g_off[NN] = running;
}

__global__ void k_scatter(const int* __restrict__ src, const int* __restrict__ dst) {
    int e = blockIdx.x * blockDim.x + threadIdx.x;
    if (e >= EE) return;
    int t = dst[e];
    int pos = atomicAdd(&g_cur[t], 1);
    g_esrc[pos] = src[e];
}

// ---------------- fused conversions (inputs + 6 weights) ----------------
__global__ void k_cvt(const float* __restrict__ in,
                      const float* __restrict__ w0, const float* __restrict__ w1,
                      const float* __restrict__ w2, const float* __restrict__ w3,
                      const float* __restrict__ w4, const float* __restrict__ w5) {
    int z = blockIdx.z;
    int idx = blockIdx.x * blockDim.x + threadIdx.x;
    if (z == 0) {
        if (idx >= NN * FIN / 4) return;
        float4 v = ((const float4*)in)[idx];
        __nv_bfloat162 lo = __floats2bfloat162_rn(v.x, v.y);
        __nv_bfloat162 hi = __floats2bfloat162_rn(v.z, v.w);
        uint32_t* o = (uint32_t*)g_xb;
        o[idx * 2 + 0] = *(uint32_t*)&lo;
        o[idx * 2 + 1] = *(uint32_t*)&hi;
    } else {
        int zz = z - 1;
        const float* w = (zz == 0) ? w0 : (zz == 1) ? w1 : (zz == 2) ? w2
                       : (zz == 3) ? w3 : (zz == 4) ? w4 : w5;
        int K = (zz < 2) ? FIN : HD;
        if (idx >= K * HD) return;
        int nq = idx / K, k = idx - nq * K;
        g_wT[(size_t)zz * HD * HD + (size_t)nq * K + k] =
            __float2bfloat16(w[(size_t)k * HD + nq]);
    }
}

// ---------------- bf16 tensor-core MERGED dual GEMM (ldmatrix frags) -------
// One block computes BOTH C0 = A@B0^T and C1 = A@B1^T for its (row,col) tile,
// loading the shared A tile once. 2 barriers amortize over 32 MMAs.
#define TBM 128
#define TBN 64
#define TBK 32
#define ASTR 20
#define BSTR 20

__device__ __forceinline__ void ldsm4(uint32_t& r0, uint32_t& r1,
                                      uint32_t& r2, uint32_t& r3, uint32_t addr) {
    asm volatile("ldmatrix.sync.aligned.m8n8.x4.shared.b16 {%0,%1,%2,%3}, [%4];"
                 : "=r"(r0), "=r"(r1), "=r"(r2), "=r"(r3) : "r"(addr));
}

__device__ __forceinline__ void mma16816(float* c, const uint32_t* a, const uint32_t* b) {
    asm volatile(
        "mma.sync.aligned.m16n8k16.row.col.f32.bf16.bf16.f32 "
        "{%0,%1,%2,%3}, {%4,%5,%6,%7}, {%8,%9}, {%0,%1,%2,%3};"
        : "+f"(c[0]), "+f"(c[1]), "+f"(c[2]), "+f"(c[3])
        : "r"(a[0]), "r"(a[1]), "r"(a[2]), "r"(a[3]), "r"(b[0]), "r"(b[1]));
}

__global__ void __launch_bounds__(256, 6)
k_gemm(const __nv_bfloat16* __restrict__ A,
       const __nv_bfloat16* __restrict__ BT0,
       const __nv_bfloat16* __restrict__ BT1,
       __nv_bfloat16* __restrict__ C0, __nv_bfloat16* __restrict__ C1,
       int M, int K, int Nc) {
    __shared__ uint32_t As[TBM * ASTR];
    __shared__ uint32_t Bs[2][TBN * BSTR];

    int tid = threadIdx.x;
    int warp = tid >> 5, lane = tid & 31;
    int warp_m = warp & 3, warp_n = warp >> 2;
    int row0 = blockIdx.y * TBM;
    int col0 = blockIdx.x * TBN;
    int gid = lane >> 2, tig = lane & 3;

    // per-lane ldmatrix addresses (byte addresses into shared)
    uint32_t s_as = (uint32_t)__cvta_generic_to_shared(As);
    uint32_t s_b0 = (uint32_t)__cvta_generic_to_shared(Bs[0]);
    uint32_t s_b1 = (uint32_t)__cvta_generic_to_shared(Bs[1]);
    int a_mrow = (lane & 7) + ((lane >> 3) & 1) * 8;
    int a_kcol = (lane >> 4) * 8;                        // elements
    uint32_t aaddr[2], baddr[2][2];
#pragma unroll
    for (int mt = 0; mt < 2; mt++)
        aaddr[mt] = s_as + (uint32_t)((warp_m * 32 + mt * 16 + a_mrow) * (ASTR * 4)
                                      + a_kcol * 2);
    int b_nrow = (lane & 7) + (lane >> 4) * 8;
    int b_kcol = ((lane >> 3) & 1) * 8;
#pragma unroll
    for (int pr = 0; pr < 2; pr++) {
        uint32_t boff = (uint32_t)((warp_n * 32 + pr * 16 + b_nrow) * (BSTR * 4)
                                   + b_kcol * 2);
        baddr[0][pr] = s_b0 + boff;
        baddr[1][pr] = s_b1 + boff;
    }

    float acc[2][2][4][4] = {};   // [which C][mt][nt][4]

    for (int k0 = 0; k0 < K; k0 += TBK) {
        // A tile: 512 uint4 chunks, 2/thread
#pragma unroll
        for (int j = 0; j < 2; j++) {
            int c = tid + j * 256;
            int r = c >> 2, q = c & 3;
            uint4 v = make_uint4(0, 0, 0, 0);
            if (row0 + r < M)
                v = *(const uint4*)(A + (size_t)(row0 + r) * K + k0 + q * 8);
            *(uint4*)&As[r * ASTR + q * 4] = v;
        }
        // B0 + B1 tiles: 256 chunks each, 1/thread each
        {
            int n = tid >> 2, q = tid & 3;
            uint4 v0 = *(const uint4*)(BT0 + (size_t)(col0 + n) * K + k0 + q * 8);
            uint4 v1 = *(const uint4*)(BT1 + (size_t)(col0 + n) * K + k0 + q * 8);
            *(uint4*)&Bs[0][n * BSTR + q * 4] = v0;
            *(uint4*)&Bs[1][n * BSTR + q * 4] = v1;
        }
        __syncthreads();

#pragma unroll
        for (int ks = 0; ks < 2; ks++) {
            uint32_t koff = ks * 32;   // 16 elements * 2 bytes per k16-step
            uint32_t a[2][4], b[2][4][2];
#pragma unroll
            for (int mt = 0; mt < 2; mt++)
                ldsm4(a[mt][0], a[mt][1], a[mt][2], a[mt][3], aaddr[mt] + koff);
#pragma unroll
            for (int w2 = 0; w2 < 2; w2++)
#pragma unroll
                for (int pr = 0; pr < 2; pr++)
                    ldsm4(b[w2][2 * pr][0], b[w2][2 * pr][1],
                          b[w2][2 * pr + 1][0], b[w2][2 * pr + 1][1],
                          baddr[w2][pr] + koff);
#pragma unroll
            for (int w2 = 0; w2 < 2; w2++)
#pragma unroll
                for (int mt = 0; mt < 2; mt++)
#pragma unroll
                    for (int nt = 0; nt < 4; nt++)
                        mma16816(acc[w2][mt][nt], a[mt], b[w2][nt]);
        }
        __syncthreads();
    }

    // epilogue: both outputs
#pragma unroll
    for (int w2 = 0; w2 < 2; w2++) {
        uint32_t* C32 = (uint32_t*)(w2 ? C1 : C0);
#pragma unroll
        for (int mt = 0; mt < 2; mt++) {
            int r = row0 + warp_m * 32 + mt * 16 + gid;
#pragma unroll
            for (int nt = 0; nt < 4; nt++) {
                int cn = col0 + warp_n * 32 + nt * 8 + tig * 2;
                if (r < M) {
                    __nv_bfloat162 p = __floats2bfloat162_rn(acc[w2][mt][nt][0],
                                                             acc[w2][mt][nt][1]);
                    C32[((size_t)r * Nc + cn) >> 1] = *(uint32_t*)&p;
                }
                if (r + 8 < M) {
                    __nv_bfloat162 p = __floats2bfloat162_rn(acc[w2][mt][nt][2],
                                                             acc[w2][mt][nt][3]);
                    C32[((size_t)(r + 8) * Nc + cn) >> 1] = *(uint32_t*)&p;
                }
            }
        }
    }
}

// ---------------- GATv2 edge softmax + aggregation (16 lanes/edge) --------
__device__ __forceinline__ float bflo(uint32_t u) { return __uint_as_float(u << 16); }
__device__ __forceinline__ float bfhi(uint32_t u) { return __uint_as_float(u & 0xFFFF0000u); }

__global__ void k_gat(const float* __restrict__ attn, const float* __restrict__ bias) {
    int w = (blockIdx.x * blockDim.x + threadIdx.x) >> 5;
    int lane = threadIdx.x & 31;
    if (w >= NN * NH) return;
    int n = w / NH, h = w - n * NH;
    int grp = lane >> 4, sub = lane & 15;
    int off = h * 32 + sub * 2;                       // u32 offset in 96-u32 row
    const uint32_t* FS = (const uint32_t*)g_fs;

    uint2 fdu = *(const uint2*)((const uint32_t*)g_fd + (size_t)n * 96 + off);
    float fd0 = bflo(fdu.x), fd1 = bfhi(fdu.x), fd2 = bflo(fdu.y), fd3 = bfhi(fdu.y);
    float4 a4 = __ldg((const float4*)(attn + h * DD + sub * 4));

    float den = 0.f, ac0 = 0.f, ac1 = 0.f, ac2 = 0.f, ac3 = 0.f;
    int beg = g_off[n], end = g_off[n + 1];

    for (int cur = beg; cur < end; cur += 4) {
        int i0 = cur + grp;
        int i1 = cur + 2 + grp;
        bool v0 = i0 < end, v1 = i1 < end;
        int s0 = __ldg(&g_esrc[v0 ? i0 : beg]);
        int s1 = __ldg(&g_esrc[v1 ? i1 : beg]);
        uint2 u0 = *(const uint2*)(FS + (size_t)s0 * 96 + off);
        uint2 u1 = *(const uint2*)(FS + (size_t)s1 * 96 + off);
        float f00 = bflo(u0.x), f01 = bfhi(u0.x), f02 = bflo(u0.y), f03 = bfhi(u0.y);
        float f10 = bflo(u1.x), f11 = bfhi(u1.x), f12 = bflo(u1.y), f13 = bfhi(u1.y);

        float t, p0, p1;
        t = f00 + fd0; t = fmaxf(t, 0.2f * t); p0 = a4.x * t;
        t = f01 + fd1; t = fmaxf(t, 0.2f * t); p0 = fmaf(a4.y, t, p0);
        t = f02 + fd2; t = fmaxf(t, 0.2f * t); p0 = fmaf(a4.z, t, p0);
        t = f03 + fd3; t = fmaxf(t, 0.2f * t); p0 = fmaf(a4.w, t, p0);
        t = f10 + fd0; t = fmaxf(t, 0.2f * t); p1 = a4.x * t;
        t = f11 + fd1; t = fmaxf(t, 0.2f * t); p1 = fmaf(a4.y, t, p1);
        t = f12 + fd2; t = fmaxf(t, 0.2f * t); p1 = fmaf(a4.z, t, p1);
        t = f13 + fd3; t = fmaxf(t, 0.2f * t); p1 = fmaf(a4.w, t, p1);
#pragma unroll
        for (int o = 1; o < 16; o <<= 1) {
            p0 += __shfl_xor_sync(0xFFFFFFFFu, p0, o);
            p1 += __shfl_xor_sync(0xFFFFFFFFu, p1, o);
        }
        float e0 = v0 ? __expf(p0) : 0.f;
        float e1 = v1 ? __expf(p1) : 0.f;
        den += e0 + e1;
        ac0 = fmaf(e0, f00, ac0); ac0 = fmaf(e1, f10, ac0);
        ac1 = fmaf(e0, f01, ac1); ac1 = fmaf(e1, f11, ac1);
        ac2 = fmaf(e0, f02, ac2); ac2 = fmaf(e1, f12, ac2);
        ac3 = fmaf(e0, f03, ac3); ac3 = fmaf(e1, f13, ac3);
    }

    den += __shfl_xor_sync(0xFFFFFFFFu, den, 16);
    ac0 += __shfl_xor_sync(0xFFFFFFFFu, ac0, 16);
    ac1 += __shfl_xor_sync(0xFFFFFFFFu, ac1, 16);
    ac2 += __shfl_xor_sync(0xFFFFFFFFu, ac2, 16);
    ac3 += __shfl_xor_sync(0xFFFFFFFFu, ac3, 16);

    float inv = 1.f / fmaxf(den, 1e-9f);
    float4 b4 = __ldg((const float4*)(bias + h * DD + sub * 4));
    float o0 = fmaf(ac0, inv, b4.x);
    float o1 = fmaf(ac1, inv, b4.y);
    float o2 = fmaf(ac2, inv, b4.z);
    float o3 = fmaf(ac3, inv, b4.w);

    if (grp == 0) {
        __nv_bfloat162 pk0 = __floats2bfloat162_rn(o0, o1);
        __nv_bfloat162 pk1 = __floats2bfloat162_rn(o2, o3);
        uint2 st;
        st.x = *(uint32_t*)&pk0;
        st.y = *(uint32_t*)&pk1;
        *(uint2*)((uint32_t*)g_xb + (size_t)n * 96 + off) = st;
    }
}

// layer-3: mean over heads (bf16 h) + graph pooling
__global__ void k_poolmean(const int* __restrict__ gid) {
    int idx = blockIdx.x * blockDim.x + threadIdx.x;
    if (idx >= NN * DD) return;
    int n = idx / DD, d = idx - n * DD;
    const __nv_bfloat16* p = g_xb + (size_t)n * HD;
    float v = (__bfloat162float(p[d]) + __bfloat162float(p[DD + d]) +
               __bfloat162float(p[2 * DD + d])) * (1.0f / 3.0f);
    int g = __ldg(&gid[n]);
    atomicAdd(&g_gsum[g * DD + d], v);
    if (d == 0) atomicAdd(&g_gcnt[g], 1.0f);
}

// ---------------- pattern branch + classifier head ----------------
__global__ void k_head(const float* __restrict__ p1, const float* __restrict__ p2,
                       const float* __restrict__ p3,
                       const float* __restrict__ Wex, const float* __restrict__ bex,
                       const float* __restrict__ Wpat, const float* __restrict__ bpat,
                       const float* __restrict__ Wc1, const float* __restrict__ bc1,
                       const float* __restrict__ Wc2, const float* __restrict__ bc2,
                       const float* __restrict__ Wc3, const float* __restrict__ bc3,
                       float* __restrict__ out) {
    int g = blockIdx.x;
    int tid = threadIdx.x;
    __shared__ float s_ex[96];
    __shared__ float s_x[128];
    __shared__ float s_c1[64];
    __shared__ float s_c2[32];

    if (tid < 96) {
        int part = tid / 32, j = tid % 32;
        const float* p = (part == 0) ? p1 : (part == 1) ? p2 : p3;
        float acc = bex[j];
        for (int k = 0; k < PP; k++) acc = fmaf(p[g * PP + k], Wex[k * 32 + j], acc);
        s_ex[tid] = acc;
    }
    __syncthreads();

    if (tid < 64) {
        float cnt = fmaxf(g_gcnt[g], 1.0f);
        s_x[tid] = g_gsum[g * DD + tid] / cnt;
    } else {
        int j = tid - 64;
        float acc = bpat[j];
        for (int k = 0; k < 96; k++) acc = fmaf(s_ex[k], Wpat[k * PP + j], acc);
        s_x[tid] = acc > 0.f ? acc : 0.01f * acc;
    }
    __syncthreads();

    if (tid < 64) {
        float acc = bc1[tid];
        for (int k = 0; k < 128; k++) acc = fmaf(s_x[k], Wc1[k * 64 + tid], acc);
        s_c1[tid] = acc > 0.f ? acc : 0.01f * acc;
    }
    __syncthreads();

    if (tid < 32) {
        float acc = bc2[tid];
        for (int k = 0; k < 64; k++) acc = fmaf(s_c1[k], Wc2[k * 32 + tid], acc);
        s_c2[tid] = acc > 0.f ? acc : 0.01f * acc;
    }
    __syncthreads();

    if (tid < 2) {
        float acc = bc3[tid];
        for (int k = 0; k < 32; k++) acc = fmaf(s_c2[k], Wc3[k * 2 + tid], acc);
        out[g * 2 + tid] = acc;
    }
}

// ---------------- driver ----------------
extern "C" void kernel_launch(void* const* d_in, const int* in_sizes, int n_in,
                              void* d_out, int out_size) {
    const float* inputs = (const float*)d_in[0];
    const int*   src    = (const int*)d_in[1];
    const int*   dst    = (const int*)d_in[2];
    const int*   gid    = (const int*)d_in[3];
    const float* p1     = (const float*)d_in[4];
    const float* p2     = (const float*)d_in[5];
    const float* p3     = (const float*)d_in[6];
    const float* W1s = (const float*)d_in[7],  *W1d = (const float*)d_in[8];
    const float* a1  = (const float*)d_in[9],  *b1  = (const float*)d_in[10];
    const float* W2s = (const float*)d_in[11], *W2d = (const float*)d_in[12];
    const float* a2  = (const float*)d_in[13], *b2  = (const float*)d_in[14];
    const float* W3s = (const float*)d_in[15], *W3d = (const float*)d_in[16];
    const float* a3  = (const float*)d_in[17], *b3  = (const float*)d_in[18];
    const float* Wex = (const float*)d_in[19], *bex = (const float*)d_in[20];
    const float* Wpat= (const float*)d_in[21], *bpat= (const float*)d_in[22];
    const float* Wc1 = (const float*)d_in[23], *bc1 = (const float*)d_in[24];
    const float* Wc2 = (const float*)d_in[25], *bc2 = (const float*)d_in[26];
    const float* Wc3 = (const float*)d_in[27], *bc3 = (const float*)d_in[28];

    __nv_bfloat16 *p_fs, *p_fd, *p_xb, *p_wT;
    cudaGetSymbolAddress((void**)&p_fs, g_fs);
    cudaGetSymbolAddress((void**)&p_fd, g_fd);
    cudaGetSymbolAddress((void**)&p_xb, g_xb);
    cudaGetSymbolAddress((void**)&p_wT, g_wT);
    const int WSLOT = HD * HD;

    // one-time stream/event creation (host resources only; no device memory)
    static cudaStream_t s2 = nullptr;
    static cudaEvent_t evFork = nullptr, evJoin = nullptr;
    if (!s2) {
        cudaStreamCreateWithFlags(&s2, cudaStreamNonBlocking);
        cudaEventCreateWithFlags(&evFork, cudaEventDisableTiming);
        cudaEventCreateWithFlags(&evJoin, cudaEventDisableTiming);
    }

    const int T = 256;
    dim3 ggrid(HD / TBN, cdiv(NN, TBM));   // merged: no z dimension
    int gat_grid = cdiv(NN * NH * 32, T);

    // fork: CSR build on s2, concurrent with cvt + GEMM1 on the main stream
    cudaEventRecord(evFork, 0);
    cudaStreamWaitEvent(s2, evFork, 0);
    k_init<<<cdiv(NN, T), T, 0, s2>>>();
    k_hist<<<cdiv(EE, T), T, 0, s2>>>(dst);
    k_scan<<<1, 1024, 0, s2>>>();
    k_scatter<<<cdiv(EE, T), T, 0, s2>>>(src, dst);
    cudaEventRecord(evJoin, s2);

    k_cvt<<<dim3(cdiv(NN * FIN / 4, T), 1, 7), T>>>(inputs, W1s, W1d, W2s, W2d, W3s, W3d);
    k_gemm<<<ggrid, 256>>>(p_xb, p_wT, p_wT + WSLOT, p_fs, p_fd, NN, FIN, HD);

    // join: gat needs the CSR
    cudaStreamWaitEvent(0, evJoin, 0);

    k_gat<<<gat_grid, T>>>(a1, b1);
    k_gemm<<<ggrid, 256>>>(p_xb, p_wT + 2 * WSLOT, p_wT + 3 * WSLOT, p_fs, p_fd, NN, HD, HD);
    k_gat<<<gat_grid, T>>>(a2, b2);
    k_gemm<<<ggrid, 256>>>(p_xb, p_wT + 4 * WSLOT, p_wT + 5 * WSLOT, p_fs, p_fd, NN, HD, HD);
    k_gat<<<gat_grid, T>>>(a3, b3);

    k_poolmean<<<cdiv(NN * DD, T), T>>>(gid);
    k_head<<<GG, 128>>>(p1, p2, p3, Wex, bex, Wpat, bpat,
                        Wc1, bc1, Wc2, bc2, Wc3, bc3, (float*)d_out);
}

// round 16
// speedup vs baseline: 2.2295x; 2.2295x over previous
#include <cuda_runtime.h>
#include <cuda_bf16.h>
#include <math.h>
#include <stdint.h>

// Problem constants (fixed by the reference)
#define NN   50000
#define EE   400000
#define FIN  128
#define NH   3
#define DD   64
#define HD   192   // NH*DD
#define GG   64
#define PP   64

// ---------------- scratch (device globals; no allocation) ----------------
__device__ __nv_bfloat16 g_fs[(size_t)NN * HD];   // GEMM outputs, bf16
__device__ __nv_bfloat16 g_fd[(size_t)NN * HD];
__device__ __nv_bfloat16 g_xb[(size_t)NN * HD];   // bf16 activations (GEMM A input)
__device__ __nv_bfloat16 g_wT[6 * HD * HD];       // 6 transposed bf16 weight mats [N][K]
__device__ float g_gsum[GG * DD];
__device__ float g_gcnt[GG];
// CSR by dst (rebuilt every launch)
__device__ int g_deg[NN];
__device__ int g_off[NN + 1];
__device__ int g_cur[NN];
__device__ int g_esrc[EE];

static inline int cdiv(int a, int b) { return (a + b - 1) / b; }

// ---------------- CSR build (4 kernels, run on side stream) ----------------
__global__ void k_init() {
    int idx = blockIdx.x * blockDim.x + threadIdx.x;
    if (idx < NN) g_deg[idx] = 0;
    if (idx < GG * DD) g_gsum[idx] = 0.0f;
    if (idx < GG) g_gcnt[idx] = 0.0f;
}

__global__ void k_hist(const int* __restrict__ dst) {
    int e = blockIdx.x * blockDim.x + threadIdx.x;
    if (e < EE) atomicAdd(&g_deg[dst[e]], 1);
}

__global__ void k_scan() {
    __shared__ int s_warp[32];
    int tid = threadIdx.x;
    int lane = tid & 31, wid = tid >> 5;
    int running = 0;
    for (int base = 0; base < NN; base += 1024) {
        int i = base + tid;
        int v = (i < NN) ? g_deg[i] : 0;
        int x = v;
#pragma unroll
        for (int o = 1; o < 32; o <<= 1) {
            int y = __shfl_up_sync(0xFFFFFFFFu, x, o);
            if (lane >= o) x += y;
        }
        if (lane == 31) s_warp[wid] = x;
        __syncthreads();
        if (wid == 0) {
            int w = s_warp[lane];
#pragma unroll
            for (int o = 1; o < 32; o <<= 1) {
                int y = __shfl_up_sync(0xFFFFFFFFu, w, o);
                if (lane >= o) w += y;
            }
            s_warp[lane] = w;
        }
        __syncthreads();
        int excl = running + x - v + (wid > 0 ? s_warp[wid - 1] : 0);
        if (i < NN) { g_off[i] = excl; g_cur[i] = excl; }
        int total = s_warp[31];
        __syncthreads();
        running += total;
    }
    if (tid == 0) g_off[NN] = running;
}

__global__ void k_scatter(const int* __restrict__ src, const int* __restrict__ dst) {
    int e = blockIdx.x * blockDim.x + threadIdx.x;
    if (e >= EE) return;
    int t = dst[e];
    int pos = atomicAdd(&g_cur[t], 1);
    g_esrc[pos] = src[e];
}

// ---------------- fused conversions (inputs + 6 weights) ----------------
__global__ void k_cvt(const float* __restrict__ in,
                      const float* __restrict__ w0, const float* __restrict__ w1,
                      const float* __restrict__ w2, const float* __restrict__ w3,
                      const float* __restrict__ w4, const float* __restrict__ w5) {
    int z = blockIdx.z;
    int idx = blockIdx.x * blockDim.x + threadIdx.x;
    if (z == 0) {
        if (idx >= NN * FIN / 4) return;
        float4 v = ((const float4*)in)[idx];
        __nv_bfloat162 lo = __floats2bfloat162_rn(v.x, v.y);
        __nv_bfloat162 hi = __floats2bfloat162_rn(v.z, v.w);
        uint32_t* o = (uint32_t*)g_xb;
        o[idx * 2 + 0] = *(uint32_t*)&lo;
        o[idx * 2 + 1] = *(uint32_t*)&hi;
    } else {
        int zz = z - 1;
        const float* w = (zz == 0) ? w0 : (zz == 1) ? w1 : (zz == 2) ? w2
                       : (zz == 3) ? w3 : (zz == 4) ? w4 : w5;
        int K = (zz < 2) ? FIN : HD;
        if (idx >= K * HD) return;
        int nq = idx / K, k = idx - nq * K;
        g_wT[(size_t)zz * HD * HD + (size_t)nq * K + k] =
            __float2bfloat16(w[(size_t)k * HD + nq]);
    }
}

// ---------------- bf16 tensor-core MERGED dual GEMM (ldmatrix frags) -------
// One block computes BOTH C0 = A@B0^T and C1 = A@B1^T for its (row,col) tile,
// loading the shared A tile once. 2 barriers amortize over 32 MMAs.
// __launch_bounds__(256, 2): <=128 regs/thread -> no spill (R14's bug was
// forcing 6 blocks/SM = 42-reg cap -> full accumulator spill).
#define TBM 128
#define TBN 64
#define TBK 32
#define ASTR 20
#define BSTR 20

__device__ __forceinline__ void ldsm4(uint32_t& r0, uint32_t& r1,
                                      uint32_t& r2, uint32_t& r3, uint32_t addr) {
    asm volatile("ldmatrix.sync.aligned.m8n8.x4.shared.b16 {%0,%1,%2,%3}, [%4];"
                 : "=r"(r0), "=r"(r1), "=r"(r2), "=r"(r3) : "r"(addr));
}

__device__ __forceinline__ void mma16816(float* c, const uint32_t* a, const uint32_t* b) {
    asm volatile(
        "mma.sync.aligned.m16n8k16.row.col.f32.bf16.bf16.f32 "
        "{%0,%1,%2,%3}, {%4,%5,%6,%7}, {%8,%9}, {%0,%1,%2,%3};"
        : "+f"(c[0]), "+f"(c[1]), "+f"(c[2]), "+f"(c[3])
        : "r"(a[0]), "r"(a[1]), "r"(a[2]), "r"(a[3]), "r"(b[0]), "r"(b[1]));
}

__global__ void __launch_bounds__(256, 2)
k_gemm(const __nv_bfloat16* __restrict__ A,
       const __nv_bfloat16* __restrict__ BT0,
       const __nv_bfloat16* __restrict__ BT1,
       __nv_bfloat16* __restrict__ C0, __nv_bfloat16* __restrict__ C1,
       int M, int K, int Nc) {
    __shared__ uint32_t As[TBM * ASTR];
    __shared__ uint32_t Bs[2][TBN * BSTR];

    int tid = threadIdx.x;
    int warp = tid >> 5, lane = tid & 31;
    int warp_m = warp & 3, warp_n = warp >> 2;
    int row0 = blockIdx.y * TBM;
    int col0 = blockIdx.x * TBN;
    int gid = lane >> 2, tig = lane & 3;

    // per-lane ldmatrix addresses (byte addresses into shared)
    uint32_t s_as = (uint32_t)__cvta_generic_to_shared(As);
    uint32_t s_b0 = (uint32_t)__cvta_generic_to_shared(Bs[0]);
    uint32_t s_b1 = (uint32_t)__cvta_generic_to_shared(Bs[1]);
    int a_mrow = (lane & 7) + ((lane >> 3) & 1) * 8;
    int a_kcol = (lane >> 4) * 8;                        // elements
    uint32_t aaddr[2], baddr[2][2];
#pragma unroll
    for (int mt = 0; mt < 2; mt++)
        aaddr[mt] = s_as + (uint32_t)((warp_m * 32 + mt * 16 + a_mrow) * (ASTR * 4)
                                      + a_kcol * 2);
    int b_nrow = (lane & 7) + (lane >> 4) * 8;
    int b_kcol = ((lane >> 3) & 1) * 8;
#pragma unroll
    for (int pr = 0; pr < 2; pr++) {
        uint32_t boff = (uint32_t)((warp_n * 32 + pr * 16 + b_nrow) * (BSTR * 4)
                                   + b_kcol * 2);
        baddr[0][pr] = s_b0 + boff;
        baddr[1][pr] = s_b1 + boff;
    }

    float acc[2][2][4][4] = {};   // [which C][mt][nt][4]

    for (int k0 = 0; k0 < K; k0 += TBK) {
        // A tile: 512 uint4 chunks, 2/thread
#pragma unroll
        for (int j = 0; j < 2; j++) {
            int c = tid + j * 256;
            int r = c >> 2, q = c & 3;
            uint4 v = make_uint4(0, 0, 0, 0);
            if (row0 + r < M)
                v = *(const uint4*)(A + (size_t)(row0 + r) * K + k0 + q * 8);
            *(uint4*)&As[r * ASTR + q * 4] = v;
        }
        // B0 + B1 tiles: 256 chunks each, 1/thread each
        {
            int n = tid >> 2, q = tid & 3;
            uint4 v0 = *(const uint4*)(BT0 + (size_t)(col0 + n) * K + k0 + q * 8);
            uint4 v1 = *(const uint4*)(BT1 + (size_t)(col0 + n) * K + k0 + q * 8);
            *(uint4*)&Bs[0][n * BSTR + q * 4] = v0;
            *(uint4*)&Bs[1][n * BSTR + q * 4] = v1;
        }
        __syncthreads();

#pragma unroll
        for (int ks = 0; ks < 2; ks++) {
            uint32_t koff = ks * 32;   // 16 elements * 2 bytes per k16-step
            uint32_t a[2][4], b[2][4][2];
#pragma unroll
            for (int mt = 0; mt < 2; mt++)
                ldsm4(a[mt][0], a[mt][1], a[mt][2], a[mt][3], aaddr[mt] + koff);
#pragma unroll
            for (int w2 = 0; w2 < 2; w2++)
#pragma unroll
                for (int pr = 0; pr < 2; pr++)
                    ldsm4(b[w2][2 * pr][0], b[w2][2 * pr][1],
                          b[w2][2 * pr + 1][0], b[w2][2 * pr + 1][1],
                          baddr[w2][pr] + koff);
#pragma unroll
            for (int w2 = 0; w2 < 2; w2++)
#pragma unroll
                for (int mt = 0; mt < 2; mt++)
#pragma unroll
                    for (int nt = 0; nt < 4; nt++)
                        mma16816(acc[w2][mt][nt], a[mt], b[w2][nt]);
        }
        __syncthreads();
    }

    // epilogue: both outputs
#pragma unroll
    for (int w2 = 0; w2 < 2; w2++) {
        uint32_t* C32 = (uint32_t*)(w2 ? C1 : C0);
#pragma unroll
        for (int mt = 0; mt < 2; mt++) {
            int r = row0 + warp_m * 32 + mt * 16 + gid;
#pragma unroll
            for (int nt = 0; nt < 4; nt++) {
                int cn = col0 + warp_n * 32 + nt * 8 + tig * 2;
                if (r < M) {
                    __nv_bfloat162 p = __floats2bfloat162_rn(acc[w2][mt][nt][0],
                                                             acc[w2][mt][nt][1]);
                    C32[((size_t)r * Nc + cn) >> 1] = *(uint32_t*)&p;
                }
                if (r + 8 < M) {
                    __nv_bfloat162 p = __floats2bfloat162_rn(acc[w2][mt][nt][2],
                                                             acc[w2][mt][nt][3]);
                    C32[((size_t)(r + 8) * Nc + cn) >> 1] = *(uint32_t*)&p;
                }
            }
        }
    }
}

// ---------------- GATv2 edge softmax + aggregation (16 lanes/edge) --------
__device__ __forceinline__ float bflo(uint32_t u) { return __uint_as_float(u << 16); }
__device__ __forceinline__ float bfhi(uint32_t u) { return __uint_as_float(u & 0xFFFF0000u); }

__global__ void k_gat(const float* __restrict__ attn, const float* __restrict__ bias) {
    int w = (blockIdx.x * blockDim.x + threadIdx.x) >> 5;
    int lane = threadIdx.x & 31;
    if (w >= NN * NH) return;
    int n = w / NH, h = w - n * NH;
    int grp = lane >> 4, sub = lane & 15;
    int off = h * 32 + sub * 2;                       // u32 offset in 96-u32 row
    const uint32_t* FS = (const uint32_t*)g_fs;

    uint2 fdu = *(const uint2*)((const uint32_t*)g_fd + (size_t)n * 96 + off);
    float fd0 = bflo(fdu.x), fd1 = bfhi(fdu.x), fd2 = bflo(fdu.y), fd3 = bfhi(fdu.y);
    float4 a4 = __ldg((const float4*)(attn + h * DD + sub * 4));

    float den = 0.f, ac0 = 0.f, ac1 = 0.f, ac2 = 0.f, ac3 = 0.f;
    int beg = g_off[n], end = g_off[n + 1];

    for (int cur = beg; cur < end; cur += 4) {
        int i0 = cur + grp;
        int i1 = cur + 2 + grp;
        bool v0 = i0 < end, v1 = i1 < end;
        int s0 = __ldg(&g_esrc[v0 ? i0 : beg]);
        int s1 = __ldg(&g_esrc[v1 ? i1 : beg]);
        uint2 u0 = *(const uint2*)(FS + (size_t)s0 * 96 + off);
        uint2 u1 = *(const uint2*)(FS + (size_t)s1 * 96 + off);
        float f00 = bflo(u0.x), f01 = bfhi(u0.x), f02 = bflo(u0.y), f03 = bfhi(u0.y);
        float f10 = bflo(u1.x), f11 = bfhi(u1.x), f12 = bflo(u1.y), f13 = bfhi(u1.y);

        float t, p0, p1;
        t = f00 + fd0; t = fmaxf(t, 0.2f * t); p0 = a4.x * t;
        t = f01 + fd1; t = fmaxf(t, 0.2f * t); p0 = fmaf(a4.y, t, p0);
        t = f02 + fd2; t = fmaxf(t, 0.2f * t); p0 = fmaf(a4.z, t, p0);
        t = f03 + fd3; t = fmaxf(t, 0.2f * t); p0 = fmaf(a4.w, t, p0);
        t = f10 + fd0; t = fmaxf(t, 0.2f * t); p1 = a4.x * t;
        t = f11 + fd1; t = fmaxf(t, 0.2f * t); p1 = fmaf(a4.y, t, p1);
        t = f12 + fd2; t = fmaxf(t, 0.2f * t); p1 = fmaf(a4.z, t, p1);
        t = f13 + fd3; t = fmaxf(t, 0.2f * t); p1 = fmaf(a4.w, t, p1);
#pragma unroll
        for (int o = 1; o < 16; o <<= 1) {
            p0 += __shfl_xor_sync(0xFFFFFFFFu, p0, o);
            p1 += __shfl_xor_sync(0xFFFFFFFFu, p1, o);
        }
        float e0 = v0 ? __expf(p0) : 0.f;
        float e1 = v1 ? __expf(p1) : 0.f;
        den += e0 + e1;
        ac0 = fmaf(e0, f00, ac0); ac0 = fmaf(e1, f10, ac0);
        ac1 = fmaf(e0, f01, ac1); ac1 = fmaf(e1, f11, ac1);
        ac2 = fmaf(e0, f02, ac2); ac2 = fmaf(e1, f12, ac2);
        ac3 = fmaf(e0, f03, ac3); ac3 = fmaf(e1, f13, ac3);
    }

    den += __shfl_xor_sync(0xFFFFFFFFu, den, 16);
    ac0 += __shfl_xor_sync(0xFFFFFFFFu, ac0, 16);
    ac1 += __shfl_xor_sync(0xFFFFFFFFu, ac1, 16);
    ac2 += __shfl_xor_sync(0xFFFFFFFFu, ac2, 16);
    ac3 += __shfl_xor_sync(0xFFFFFFFFu, ac3, 16);

    float inv = 1.f / fmaxf(den, 1e-9f);
    float4 b4 = __ldg((const float4*)(bias + h * DD + sub * 4));
    float o0 = fmaf(ac0, inv, b4.x);
    float o1 = fmaf(ac1, inv, b4.y);
    float o2 = fmaf(ac2, inv, b4.z);
    float o3 = fmaf(ac3, inv, b4.w);

    if (grp == 0) {
        __nv_bfloat162 pk0 = __floats2bfloat162_rn(o0, o1);
        __nv_bfloat162 pk1 = __floats2bfloat162_rn(o2, o3);
        uint2 st;
        st.x = *(uint32_t*)&pk0;
        st.y = *(uint32_t*)&pk1;
        *(uint2*)((uint32_t*)g_xb + (size_t)n * 96 + off) = st;
    }
}

// layer-3: mean over heads (bf16 h) + graph pooling
__global__ void k_poolmean(const int* __restrict__ gid) {
    int idx = blockIdx.x * blockDim.x + threadIdx.x;
    if (idx >= NN * DD) return;
    int n = idx / DD, d = idx - n * DD;
    const __nv_bfloat16* p = g_xb + (size_t)n * HD;
    float v = (__bfloat162float(p[d]) + __bfloat162float(p[DD + d]) +
               __bfloat162float(p[2 * DD + d])) * (1.0f / 3.0f);
    int g = __ldg(&gid[n]);
    atomicAdd(&g_gsum[g * DD + d], v);
    if (d == 0) atomicAdd(&g_gcnt[g], 1.0f);
}

// ---------------- pattern branch + classifier head ----------------
__global__ void k_head(const float* __restrict__ p1, const float* __restrict__ p2,
                       const float* __restrict__ p3,
                       const float* __restrict__ Wex, const float* __restrict__ bex,
                       const float* __restrict__ Wpat, const float* __restrict__ bpat,
                       const float* __restrict__ Wc1, const float* __restrict__ bc1,
                       const float* __restrict__ Wc2, const float* __restrict__ bc2,
                       const float* __restrict__ Wc3, const float* __restrict__ bc3,
                       float* __restrict__ out) {
    int g = blockIdx.x;
    int tid = threadIdx.x;
    __shared__ float s_ex[96];
    __shared__ float s_x[128];
    __shared__ float s_c1[64];
    __shared__ float s_c2[32];

    if (tid < 96) {
        int part = tid / 32, j = tid % 32;
        const float* p = (part == 0) ? p1 : (part == 1) ? p2 : p3;
        float acc = bex[j];
        for (int k = 0; k < PP; k++) acc = fmaf(p[g * PP + k], Wex[k * 32 + j], acc);
        s_ex[tid] = acc;
    }
    __syncthreads();

    if (tid < 64) {
        float cnt = fmaxf(g_gcnt[g], 1.0f);
        s_x[tid] = g_gsum[g * DD + tid] / cnt;
    } else {
        int j = tid - 64;
        float acc = bpat[j];
        for (int k = 0; k < 96; k++) acc = fmaf(s_ex[k], Wpat[k * PP + j], acc);
        s_x[tid] = acc > 0.f ? acc : 0.01f * acc;
    }
    __syncthreads();

    if (tid < 64) {
        float acc = bc1[tid];
        for (int k = 0; k < 128; k++) acc = fmaf(s_x[k], Wc1[k * 64 + tid], acc);
        s_c1[tid] = acc > 0.f ? acc : 0.01f * acc;
    }
    __syncthreads();

    if (tid < 32) {
        float acc = bc2[tid];
        for (int k = 0; k < 64; k++) acc = fmaf(s_c1[k], Wc2[k * 32 + tid], acc);
        s_c2[tid] = acc > 0.f ? acc : 0.01f * acc;
    }
    __syncthreads();

    if (tid < 2) {
        float acc = bc3[tid];
        for (int k = 0; k < 32; k++) acc = fmaf(s_c2[k], Wc3[k * 2 + tid], acc);
        out[g * 2 + tid] = acc;
    }
}

// ---------------- driver ----------------
extern "C" void kernel_launch(void* const* d_in, const int* in_sizes, int n_in,
                              void* d_out, int out_size) {
    const float* inputs = (const float*)d_in[0];
    const int*   src    = (const int*)d_in[1];
    const int*   dst    = (const int*)d_in[2];
    const int*   gid    = (const int*)d_in[3];
    const float* p1     = (const float*)d_in[4];
    const float* p2     = (const float*)d_in[5];
    const float* p3     = (const float*)d_in[6];
    const float* W1s = (const float*)d_in[7],  *W1d = (const float*)d_in[8];
    const float* a1  = (const float*)d_in[9],  *b1  = (const float*)d_in[10];
    const float* W2s = (const float*)d_in[11], *W2d = (const float*)d_in[12];
    const float* a2  = (const float*)d_in[13], *b2  = (const float*)d_in[14];
    const float* W3s = (const float*)d_in[15], *W3d = (const float*)d_in[16];
    const float* a3  = (const float*)d_in[17], *b3  = (const float*)d_in[18];
    const float* Wex = (const float*)d_in[19], *bex = (const float*)d_in[20];
    const float* Wpat= (const float*)d_in[21], *bpat= (const float*)d_in[22];
    const float* Wc1 = (const float*)d_in[23], *bc1 = (const float*)d_in[24];
    const float* Wc2 = (const float*)d_in[25], *bc2 = (const float*)d_in[26];
    const float* Wc3 = (const float*)d_in[27], *bc3 = (const float*)d_in[28];

    __nv_bfloat16 *p_fs, *p_fd, *p_xb, *p_wT;
    cudaGetSymbolAddress((void**)&p_fs, g_fs);
    cudaGetSymbolAddress((void**)&p_fd, g_fd);
    cudaGetSymbolAddress((void**)&p_xb, g_xb);
    cudaGetSymbolAddress((void**)&p_wT, g_wT);
    const int WSLOT = HD * HD;

    // one-time stream/event creation (host resources only; no device memory)
    static cudaStream_t s2 = nullptr;
    static cudaEvent_t evFork = nullptr, evJoin = nullptr;
    if (!s2) {
        cudaStreamCreateWithFlags(&s2, cudaStreamNonBlocking);
        cudaEventCreateWithFlags(&evFork, cudaEventDisableTiming);
        cudaEventCreateWithFlags(&evJoin, cudaEventDisableTiming);
    }

    const int T = 256;
    dim3 ggrid(HD / TBN, cdiv(NN, TBM));   // merged: no z dimension
    int gat_grid = cdiv(NN * NH * 32, T);

    // fork: CSR build on s2, concurrent with cvt + GEMM1 on the main stream
    cudaEventRecord(evFork, 0);
    cudaStreamWaitEvent(s2, evFork, 0);
    k_init<<<cdiv(NN, T), T, 0, s2>>>();
    k_hist<<<cdiv(EE, T), T, 0, s2>>>(dst);
    k_scan<<<1, 1024, 0, s2>>>();
    k_scatter<<<cdiv(EE, T), T, 0, s2>>>(src, dst);
    cudaEventRecord(evJoin, s2);

    k_cvt<<<dim3(cdiv(NN * FIN / 4, T), 1, 7), T>>>(inputs, W1s, W1d, W2s, W2d, W3s, W3d);
    k_gemm<<<ggrid, 256>>>(p_xb, p_wT, p_wT + WSLOT, p_fs, p_fd, NN, FIN, HD);

    // join: gat needs the CSR
    cudaStreamWaitEvent(0, evJoin, 0);

    k_gat<<<gat_grid, T>>>(a1, b1);
    k_gemm<<<ggrid, 256>>>(p_xb, p_wT + 2 * WSLOT, p_wT + 3 * WSLOT, p_fs, p_fd, NN, HD, HD);
    k_gat<<<gat_grid, T>>>(a2, b2);
    k_gemm<<<ggrid, 256>>>(p_xb, p_wT + 4 * WSLOT, p_wT + 5 * WSLOT, p_fs, p_fd, NN, HD, HD);
    k_gat<<<gat_grid, T>>>(a3, b3);

    k_poolmean<<<cdiv(NN * DD, T), T>>>(gid);
    k_head<<<GG, 128>>>(p1, p2, p3, Wex, bex, Wpat, bpat,
                        Wc1, bc1, Wc2, bc2, Wc3, bc3, (float*)d_out);
}